// round 3
// baseline (speedup 1.0000x reference)
#include <cuda_runtime.h>
#include <cstdint>

// Problem constants (fixed by reference)
#define BATCH   4
#define NTOK    8192
#define DIM     768
#define SEGW    512
#define NSEG    16
#define MG      256      // gathered (even) rows per segment
#define TM      64       // Q rows per CTA tile
#define KC      32       // k-chunk width (phase 1)
#define DV      64       // d-chunk width (phase 3)
#define THREADS 256

// Padded smem strides (floats).
// k-major tiles: stride % 8 == 4  -> conflict-free m16n8k8 frag loads
// V (n-major rows): stride % 32 == 8 -> conflict-free B frag loads
#define K_STRIDE 36
#define P_STRIDE 260
#define V_STRIDE 72

#define P_OFF    0
#define P_FLOATS (TM * P_STRIDE)            // 16640
#define V_OFF    P_FLOATS
#define V_FLOATS (MG * V_STRIDE)            // 18432
#define SMEM_FLOATS (P_FLOATS + V_FLOATS)   // 35072
#define SMEM_BYTES  (SMEM_FLOATS * 4)       // 140288
// Phase-1 K chunk (256 x 36 = 9216 floats) aliases the P region (written later).
#define KCH_OFF 0

__device__ __forceinline__ uint32_t f2tf32(float f) {
    uint32_t u;
    asm("cvt.rna.tf32.f32 %0, %1;" : "=r"(u) : "f"(f));
    return u;
}

__device__ __forceinline__ void split_tf32(float f, uint32_t& hi, uint32_t& lo) {
    hi = f2tf32(f);
    lo = f2tf32(f - __uint_as_float(hi));
}

__device__ __forceinline__ void mma8(float c[4], const uint32_t a[4], const uint32_t b[2]) {
    asm volatile(
        "mma.sync.aligned.m16n8k8.row.col.f32.tf32.tf32.f32 "
        "{%0,%1,%2,%3}, {%4,%5,%6,%7}, {%8,%9}, {%0,%1,%2,%3};\n"
        : "+f"(c[0]), "+f"(c[1]), "+f"(c[2]), "+f"(c[3])
        : "r"(a[0]), "r"(a[1]), "r"(a[2]), "r"(a[3]), "r"(b[0]), "r"(b[1]));
}

__global__ __launch_bounds__(THREADS, 1)
void dilated_attn_kernel(const float* __restrict__ x, float* __restrict__ y)
{
    extern __shared__ float sm[];
    const int tid  = threadIdx.x;
    const int lane = tid & 31;
    const int wid  = tid >> 5;

    const int tile = blockIdx.x & 3;        // 4 row tiles of 64 per problem
    const int pid  = blockIdx.x >> 2;       // 64 problems
    const int b    = pid >> 4;
    const int seg  = pid & 15;

    const long segbase = (long)b * NTOK + (long)seg * SEGW;  // token base
    const int  q0 = tile * TM;              // offset into the 256 gathered rows

    // Warp layout (both phases): 2 m-warps x 4 n-warps
    const int wm  = wid & 1;
    const int wn  = wid >> 1;
    const int ln4 = lane >> 2;   // 0..7  (fragment "group")
    const int lc4 = lane & 3;    // 0..3  (thread-in-group)

    // ============ Phase 1: S = Q K^T  (64 x 256, k over 768) ============
    // Warp tile: 32 rows x 64 cols -> mt in {0,1}, nt in 0..7
    float acc[2][8][4];
    #pragma unroll
    for (int mt = 0; mt < 2; mt++)
        #pragma unroll
        for (int nt = 0; nt < 8; nt++)
            #pragma unroll
            for (int i = 0; i < 4; i++)
                acc[mt][nt][i] = 0.f;

    for (int kc = 0; kc < DIM / KC; kc++) {
        const int kd = kc * KC;
        // Load K chunk: 256 gathered rows x 32 cols (Q rows are a subset)
        for (int i = tid; i < MG * KC / 4; i += THREADS) {
            int r = i >> 3, c4 = i & 7;
            long tok = segbase + 2 * r;
            float4 v = *(const float4*)(x + (size_t)tok * DIM + kd + c4 * 4);
            *(float4*)(sm + KCH_OFF + r * K_STRIDE + c4 * 4) = v;
        }
        __syncthreads();

        #pragma unroll
        for (int ks = 0; ks < KC / 8; ks++) {
            const int kk = ks * 8;
            uint32_t ahi[2][4], alo[2][4];
            #pragma unroll
            for (int mt = 0; mt < 2; mt++) {
                int r = q0 + wm * 32 + mt * 16 + ln4;
                const float* ba = sm + KCH_OFF + r * K_STRIDE + kk + lc4;
                // A frag order: a0=(r,c) a1=(r+8,c) a2=(r,c+4) a3=(r+8,c+4)
                split_tf32(ba[0],              ahi[mt][0], alo[mt][0]);
                split_tf32(ba[8 * K_STRIDE],   ahi[mt][1], alo[mt][1]);
                split_tf32(ba[4],              ahi[mt][2], alo[mt][2]);
                split_tf32(ba[8 * K_STRIDE+4], ahi[mt][3], alo[mt][3]);
            }
            #pragma unroll
            for (int nt = 0; nt < 8; nt++) {
                int n = wn * 64 + nt * 8 + ln4;
                const float* bb = sm + KCH_OFF + n * K_STRIDE + kk + lc4;
                uint32_t bh[2], bl[2];
                split_tf32(bb[0], bh[0], bl[0]);
                split_tf32(bb[4], bh[1], bl[1]);
                #pragma unroll
                for (int mt = 0; mt < 2; mt++) {
                    mma8(acc[mt][nt], ahi[mt], bh);
                    mma8(acc[mt][nt], ahi[mt], bl);
                    mma8(acc[mt][nt], alo[mt], bh);
                }
            }
        }
        __syncthreads();
    }

    // ============ Phase 2: scale + softmax into P (64 x 256) ============
    const float scale = 0.03608439182435161f;  // 768^-0.5
    #pragma unroll
    for (int mt = 0; mt < 2; mt++)
        #pragma unroll
        for (int nt = 0; nt < 8; nt++) {
            int r = wm * 32 + mt * 16 + ln4;
            int c = wn * 64 + nt * 8 + 2 * lc4;
            sm[P_OFF + r * P_STRIDE + c]           = acc[mt][nt][0] * scale;
            sm[P_OFF + r * P_STRIDE + c + 1]       = acc[mt][nt][1] * scale;
            sm[P_OFF + (r + 8) * P_STRIDE + c]     = acc[mt][nt][2] * scale;
            sm[P_OFF + (r + 8) * P_STRIDE + c + 1] = acc[mt][nt][3] * scale;
        }
    __syncthreads();

    // Row softmax: warp w handles rows w*8..w*8+7; lane covers cols lane+32i
    #pragma unroll
    for (int rr = 0; rr < 8; rr++) {
        int row = wid * 8 + rr;
        float* pr = sm + P_OFF + row * P_STRIDE;
        float v[8];
        float mx = -1e30f;
        #pragma unroll
        for (int i = 0; i < 8; i++) { v[i] = pr[lane + 32 * i]; mx = fmaxf(mx, v[i]); }
        #pragma unroll
        for (int o = 16; o > 0; o >>= 1) mx = fmaxf(mx, __shfl_xor_sync(~0u, mx, o));
        float s = 0.f;
        #pragma unroll
        for (int i = 0; i < 8; i++) { v[i] = expf(v[i] - mx); s += v[i]; }
        #pragma unroll
        for (int o = 16; o > 0; o >>= 1) s += __shfl_xor_sync(~0u, s, o);
        float inv = 1.f / s;
        #pragma unroll
        for (int i = 0; i < 8; i++) pr[lane + 32 * i] = v[i] * inv;
    }
    __syncthreads();

    // ============ Phase 3: out = P V  (64 x 768, chunks of 64 cols) ============
    for (int ch = 0; ch < DIM / DV; ch++) {
        const int d0 = ch * DV;
        // Load V chunk: 256 gathered rows x 64 cols
        for (int i = tid; i < MG * DV / 4; i += THREADS) {
            int r = i >> 4, c4 = i & 15;
            long tok = segbase + 2 * r;
            float4 v = *(const float4*)(x + (size_t)tok * DIM + d0 + c4 * 4);
            *(float4*)(sm + V_OFF + r * V_STRIDE + c4 * 4) = v;
        }
        __syncthreads();

        // Warp tile: 32 rows x 16 cols -> mt in {0,1}, nt in {0,1}
        float o[2][2][4];
        #pragma unroll
        for (int mt = 0; mt < 2; mt++)
            #pragma unroll
            for (int nt = 0; nt < 2; nt++)
                #pragma unroll
                for (int i = 0; i < 4; i++)
                    o[mt][nt][i] = 0.f;

        #pragma unroll 4
        for (int ks = 0; ks < MG / 8; ks++) {
            const int kk = ks * 8;
            uint32_t ahi[2][4], alo[2][4];
            #pragma unroll
            for (int mt = 0; mt < 2; mt++) {
                int r = wm * 32 + mt * 16 + ln4;
                const float* ba = sm + P_OFF + r * P_STRIDE + kk + lc4;
                // A frag order: a0=(r,c) a1=(r+8,c) a2=(r,c+4) a3=(r+8,c+4)
                split_tf32(ba[0],              ahi[mt][0], alo[mt][0]);
                split_tf32(ba[8 * P_STRIDE],   ahi[mt][1], alo[mt][1]);
                split_tf32(ba[4],              ahi[mt][2], alo[mt][2]);
                split_tf32(ba[8 * P_STRIDE+4], ahi[mt][3], alo[mt][3]);
            }
            #pragma unroll
            for (int nt = 0; nt < 2; nt++) {
                int n = wn * 16 + nt * 8 + ln4;
                const float* bb = sm + V_OFF + (kk + lc4) * V_STRIDE + n;
                uint32_t bh[2], bl[2];
                split_tf32(bb[0],            bh[0], bl[0]);
                split_tf32(bb[4 * V_STRIDE], bh[1], bl[1]);
                #pragma unroll
                for (int mt = 0; mt < 2; mt++) {
                    mma8(o[mt][nt], ahi[mt], bh);
                    mma8(o[mt][nt], ahi[mt], bl);
                    mma8(o[mt][nt], alo[mt], bh);
                }
            }
        }

        // Write even rows (results)
        #pragma unroll
        for (int mt = 0; mt < 2; mt++)
            #pragma unroll
            for (int nt = 0; nt < 2; nt++) {
                int gr = q0 + wm * 32 + mt * 16 + ln4;
                int c  = d0 + wn * 16 + nt * 8 + 2 * lc4;
                long tok0 = segbase + 2 * (long)gr;
                long tok1 = segbase + 2 * (long)(gr + 8);
                *(float2*)(y + (size_t)tok0 * DIM + c) = make_float2(o[mt][nt][0], o[mt][nt][1]);
                *(float2*)(y + (size_t)tok1 * DIM + c) = make_float2(o[mt][nt][2], o[mt][nt][3]);
            }

        // Zero the odd partner rows for this d-chunk
        for (int i = tid; i < TM * DV / 4; i += THREADS) {
            int r = i >> 4, c4 = i & 15;
            long tok = segbase + 2 * (long)(q0 + r) + 1;
            *(float4*)(y + (size_t)tok * DIM + d0 + c4 * 4) = make_float4(0.f, 0.f, 0.f, 0.f);
        }
        __syncthreads();
    }
}

extern "C" void kernel_launch(void* const* d_in, const int* in_sizes, int n_in,
                              void* d_out, int out_size)
{
    const float* x = (const float*)d_in[0];
    float* y = (float*)d_out;
    cudaFuncSetAttribute(dilated_attn_kernel,
                         cudaFuncAttributeMaxDynamicSharedMemorySize, SMEM_BYTES);
    dilated_attn_kernel<<<BATCH * NSEG * 4, THREADS, SMEM_BYTES>>>(x, y);
}

// round 4
// speedup vs baseline: 2.5970x; 2.5970x over previous
#include <cuda_runtime.h>
#include <cstdint>

// Problem constants (fixed by reference)
#define BATCH   4
#define NTOK    8192
#define DIM     768
#define SEGW    512
#define NSEG    16
#define MG      256       // gathered (even) rows per segment
#define TM      64        // Q rows per CTA tile
#define KC      32        // phase-1 k-chunk width
#define NCHUNK  (DIM/KC)  // 24
#define THREADS 256

#define DHALF   384       // phase-3 d half-width
#define KSLAB   16        // phase-3 V slab rows
#define NSLAB   (MG/KSLAB)// 16

// Padded smem strides (floats). k-major: stride%8==4; V n-major: stride%32==8.
#define K_STRIDE 36
#define P_STRIDE 260
#define V_STRIDE 392      // 384 + 8

#define KCHF    (MG*K_STRIDE)     // 9216 floats per K buffer
#define P_OFF   0                 // P (64x260) overlaps K buffers (dead by then)
#define V_OFF   (2*KCHF)          // 18432
#define VSLABF  (KSLAB*V_STRIDE)  // 6272 floats per V buffer
#define SMEM_FLOATS (V_OFF + 2*VSLABF)      // 30976
#define SMEM_BYTES  (SMEM_FLOATS * 4)       // 123904

__device__ __forceinline__ uint32_t f2tf32(float f) {
    uint32_t u;
    asm("cvt.rna.tf32.f32 %0, %1;" : "=r"(u) : "f"(f));
    return u;
}

__device__ __forceinline__ void sts_tf32x4(float* dst, float4 v) {
    float4 w;
    w.x = __uint_as_float(f2tf32(v.x));
    w.y = __uint_as_float(f2tf32(v.y));
    w.z = __uint_as_float(f2tf32(v.z));
    w.w = __uint_as_float(f2tf32(v.w));
    *(float4*)dst = w;
}

__device__ __forceinline__ void mma8(float c[4], const uint32_t a[4], const uint32_t b[2]) {
    asm volatile(
        "mma.sync.aligned.m16n8k8.row.col.f32.tf32.tf32.f32 "
        "{%0,%1,%2,%3}, {%4,%5,%6,%7}, {%8,%9}, {%0,%1,%2,%3};\n"
        : "+f"(c[0]), "+f"(c[1]), "+f"(c[2]), "+f"(c[3])
        : "r"(a[0]), "r"(a[1]), "r"(a[2]), "r"(a[3]), "r"(b[0]), "r"(b[1]));
}

__global__ __launch_bounds__(THREADS, 1)
void dilated_attn_kernel(const float* __restrict__ x, float* __restrict__ y)
{
    extern __shared__ float sm[];
    uint32_t* smu = (uint32_t*)sm;
    const int tid  = threadIdx.x;
    const int lane = tid & 31;
    const int wid  = tid >> 5;

    const int tile = blockIdx.x & 3;        // 4 row tiles of 64 per problem
    const int pid  = blockIdx.x >> 2;       // 64 problems
    const int b    = pid >> 4;
    const int seg  = pid & 15;

    const long segbase = (long)b * NTOK + (long)seg * SEGW;  // token base
    const int  q0 = tile * TM;

    // Warp layout: 2 m-warps x 4 n-warps (both phases)
    const int wm  = wid & 1;
    const int wn  = wid >> 1;
    const int ln4 = lane >> 2;   // fragment group 0..7
    const int lc4 = lane & 3;    // thread-in-group 0..3

    // ============ Phase 1: S = Q K^T (64 x 256), double-buffered K chunks ============
    float acc[2][8][4];
    #pragma unroll
    for (int mt = 0; mt < 2; mt++)
        #pragma unroll
        for (int nt = 0; nt < 8; nt++)
            #pragma unroll
            for (int i = 0; i < 4; i++)
                acc[mt][nt][i] = 0.f;

    // Prologue: load chunk 0 into buf0 (tf32-rounded at store)
    {
        #pragma unroll
        for (int j = 0; j < 8; j++) {
            int idx = j * THREADS + tid;
            int r = idx >> 3, c4 = idx & 7;
            float4 v = *(const float4*)(x + (size_t)(segbase + 2 * r) * DIM + c4 * 4);
            sts_tf32x4(sm + r * K_STRIDE + c4 * 4, v);
        }
    }
    __syncthreads();

    float4 stg[8];
    for (int kc = 0; kc < NCHUNK; kc++) {
        const uint32_t* cur = smu + (kc & 1 ? KCHF : 0);
        const bool pf = (kc + 1 < NCHUNK);
        if (pf) {
            const int kd = (kc + 1) * KC;
            #pragma unroll
            for (int j = 0; j < 8; j++) {
                int idx = j * THREADS + tid;
                int r = idx >> 3, c4 = idx & 7;
                stg[j] = *(const float4*)(x + (size_t)(segbase + 2 * r) * DIM + kd + c4 * 4);
            }
        }
        #pragma unroll
        for (int ks = 0; ks < KC / 8; ks++) {
            const int kk = ks * 8;
            uint32_t a[2][4];
            #pragma unroll
            for (int mt = 0; mt < 2; mt++) {
                int r = q0 + wm * 32 + mt * 16 + ln4;
                const uint32_t* ba = cur + r * K_STRIDE + kk + lc4;
                a[mt][0] = ba[0];
                a[mt][1] = ba[8 * K_STRIDE];
                a[mt][2] = ba[4];
                a[mt][3] = ba[8 * K_STRIDE + 4];
            }
            #pragma unroll
            for (int nt = 0; nt < 8; nt++) {
                int n = wn * 64 + nt * 8 + ln4;
                const uint32_t* bb = cur + n * K_STRIDE + kk + lc4;
                uint32_t bf[2] = { bb[0], bb[4] };
                mma8(acc[0][nt], a[0], bf);
                mma8(acc[1][nt], a[1], bf);
            }
        }
        if (pf) {
            float* dst = sm + (kc & 1 ? 0 : KCHF);
            #pragma unroll
            for (int j = 0; j < 8; j++) {
                int idx = j * THREADS + tid;
                int r = idx >> 3, c4 = idx & 7;
                sts_tf32x4(dst + r * K_STRIDE + c4 * 4, stg[j]);
            }
        }
        __syncthreads();
    }

    // ============ Phase 2: scale + softmax into P (tf32-rounded on final write) ============
    const float scale = 0.03608439182435161f;  // 768^-0.5
    #pragma unroll
    for (int mt = 0; mt < 2; mt++)
        #pragma unroll
        for (int nt = 0; nt < 8; nt++) {
            int r = wm * 32 + mt * 16 + ln4;
            int c = wn * 64 + nt * 8 + 2 * lc4;
            sm[P_OFF + r * P_STRIDE + c]           = acc[mt][nt][0] * scale;
            sm[P_OFF + r * P_STRIDE + c + 1]       = acc[mt][nt][1] * scale;
            sm[P_OFF + (r + 8) * P_STRIDE + c]     = acc[mt][nt][2] * scale;
            sm[P_OFF + (r + 8) * P_STRIDE + c + 1] = acc[mt][nt][3] * scale;
        }
    __syncthreads();

    #pragma unroll
    for (int rr = 0; rr < 8; rr++) {
        int row = wid * 8 + rr;
        float* pr = sm + P_OFF + row * P_STRIDE;
        float v[8];
        float mx = -1e30f;
        #pragma unroll
        for (int i = 0; i < 8; i++) { v[i] = pr[lane + 32 * i]; mx = fmaxf(mx, v[i]); }
        #pragma unroll
        for (int o = 16; o > 0; o >>= 1) mx = fmaxf(mx, __shfl_xor_sync(~0u, mx, o));
        float s = 0.f;
        #pragma unroll
        for (int i = 0; i < 8; i++) { v[i] = expf(v[i] - mx); s += v[i]; }
        #pragma unroll
        for (int o = 16; o > 0; o >>= 1) s += __shfl_xor_sync(~0u, s, o);
        float inv = 1.f / s;
        #pragma unroll
        for (int i = 0; i < 8; i++)
            pr[lane + 32 * i] = __uint_as_float(f2tf32(v[i] * inv));
    }
    __syncthreads();

    // ============ Phase 3: out = P V, two d-halves, V streamed in 16-row slabs ============
    for (int half = 0; half < 2; half++) {
        const int d0 = half * DHALF;

        float o[2][12][4];
        #pragma unroll
        for (int mt = 0; mt < 2; mt++)
            #pragma unroll
            for (int nt = 0; nt < 12; nt++)
                #pragma unroll
                for (int i = 0; i < 4; i++)
                    o[mt][nt][i] = 0.f;

        // Prologue: slab 0 -> V buf0
        {
            #pragma unroll
            for (int j = 0; j < 6; j++) {
                int idx = j * THREADS + tid;
                int row = idx / 96, c4 = idx % 96;
                float4 v = *(const float4*)(x + (size_t)(segbase + 2 * row) * DIM + d0 + c4 * 4);
                sts_tf32x4(sm + V_OFF + row * V_STRIDE + c4 * 4, v);
            }
        }
        __syncthreads();

        float4 vst[6];
        for (int sl = 0; sl < NSLAB; sl++) {
            const uint32_t* vcur = smu + V_OFF + (sl & 1) * VSLABF;
            const bool pf = (sl + 1 < NSLAB);
            if (pf) {
                const int rbase = (sl + 1) * KSLAB;
                #pragma unroll
                for (int j = 0; j < 6; j++) {
                    int idx = j * THREADS + tid;
                    int row = idx / 96, c4 = idx % 96;
                    vst[j] = *(const float4*)(x + (size_t)(segbase + 2 * (rbase + row)) * DIM + d0 + c4 * 4);
                }
            }
            #pragma unroll
            for (int ki = 0; ki < KSLAB / 8; ki++) {
                const int kk = ki * 8;               // row within slab
                const int kg = sl * KSLAB + kk;      // global k
                uint32_t a[2][4];
                #pragma unroll
                for (int mt = 0; mt < 2; mt++) {
                    int r = wm * 32 + mt * 16 + ln4;
                    const uint32_t* ba = smu + P_OFF + r * P_STRIDE + kg + lc4;
                    a[mt][0] = ba[0];
                    a[mt][1] = ba[8 * P_STRIDE];
                    a[mt][2] = ba[4];
                    a[mt][3] = ba[8 * P_STRIDE + 4];
                }
                #pragma unroll
                for (int nt = 0; nt < 12; nt++) {
                    int n = wn * 96 + nt * 8 + ln4;
                    const uint32_t* bb = vcur + (kk + lc4) * V_STRIDE + n;
                    uint32_t bf[2] = { bb[0], bb[4 * V_STRIDE] };
                    mma8(o[0][nt], a[0], bf);
                    mma8(o[1][nt], a[1], bf);
                }
            }
            if (pf) {
                float* dst = sm + V_OFF + ((sl + 1) & 1) * VSLABF;
                #pragma unroll
                for (int j = 0; j < 6; j++) {
                    int idx = j * THREADS + tid;
                    int row = idx / 96, c4 = idx % 96;
                    sts_tf32x4(dst + row * V_STRIDE + c4 * 4, vst[j]);
                }
            }
            __syncthreads();
        }

        // Epilogue: even (gathered) rows get results
        #pragma unroll
        for (int mt = 0; mt < 2; mt++)
            #pragma unroll
            for (int nt = 0; nt < 12; nt++) {
                int gr = q0 + wm * 32 + mt * 16 + ln4;
                int c  = d0 + wn * 96 + nt * 8 + 2 * lc4;
                long tok0 = segbase + 2 * (long)gr;
                long tok1 = segbase + 2 * (long)(gr + 8);
                *(float2*)(y + (size_t)tok0 * DIM + c) = make_float2(o[mt][nt][0], o[mt][nt][1]);
                *(float2*)(y + (size_t)tok1 * DIM + c) = make_float2(o[mt][nt][2], o[mt][nt][3]);
            }

        // Odd partner rows are exactly zero
        for (int i = tid; i < TM * DHALF / 4; i += THREADS) {
            int r = i / 96, c4 = i % 96;
            long tok = segbase + 2 * (long)(q0 + r) + 1;
            *(float4*)(y + (size_t)tok * DIM + d0 + c4 * 4) = make_float4(0.f, 0.f, 0.f, 0.f);
        }
        __syncthreads();
    }
}

extern "C" void kernel_launch(void* const* d_in, const int* in_sizes, int n_in,
                              void* d_out, int out_size)
{
    const float* x = (const float*)d_in[0];
    float* y = (float*)d_out;
    cudaFuncSetAttribute(dilated_attn_kernel,
                         cudaFuncAttributeMaxDynamicSharedMemorySize, SMEM_BYTES);
    dilated_attn_kernel<<<BATCH * NSEG * 4, THREADS, SMEM_BYTES>>>(x, y);
}